// round 16
// baseline (speedup 1.0000x reference)
#include <cuda_runtime.h>
#include <cstdint>
#include <cstddef>

// ---------------- problem dims (fixed) ----------------
#define I_DIM   4
#define H_DIM   2048
#define O_DIM   2
#define R_DIM   2
#define S_DIM   2
#define GB_DIM  8
#define B_DIM   32
#define T_DIM   1024
#define ALPHA_C 0.2f
#define SIGMA_C 0.05f

#define NTHREADS 512
#define EPT      4          // neurons per thread: 512*4 = 2048
#define NWARPS   (NTHREADS / 32)   // 16

typedef unsigned long long u64;

// ---------------- precomputed proxy weights (device scratch) ----------------
__device__ __align__(16) float g_wi[I_DIM * H_DIM];  // alpha * wi,   layout [i][h]
__device__ __align__(16) float g_m [R_DIM * H_DIM];  // (alpha/H)*m,  layout [r][h]
__device__ __align__(16) float g_n [R_DIM * H_DIM];  // n (raw),      layout [r][h]
__device__ __align__(16) float g_wo[O_DIM * H_DIM];  // wo / H,       layout [o][h]
__device__ __align__(16) float g_h0[H_DIM];

// ---------------- packed f32x2 helpers (sm_103a) ----------------
__device__ __forceinline__ u64 pack2(float lo, float hi) {
    u64 r; asm("mov.b64 %0, {%1, %2};" : "=l"(r) : "f"(lo), "f"(hi)); return r;
}
__device__ __forceinline__ u64 dup2(float x) { return pack2(x, x); }
__device__ __forceinline__ void unpack2(u64 v, float& lo, float& hi) {
    asm("mov.b64 {%0, %1}, %2;" : "=f"(lo), "=f"(hi) : "l"(v));
}
__device__ __forceinline__ u64 fma2(u64 a, u64 b, u64 c) {
    u64 d; asm("fma.rn.f32x2 %0, %1, %2, %3;" : "=l"(d) : "l"(a), "l"(b), "l"(c)); return d;
}
__device__ __forceinline__ u64 mul2(u64 a, u64 b) {
    u64 d; asm("mul.rn.f32x2 %0, %1, %2;" : "=l"(d) : "l"(a), "l"(b)); return d;
}
__device__ __forceinline__ u64 add2(u64 a, u64 b) {
    u64 d; asm("add.rn.f32x2 %0, %1, %2;" : "=l"(d) : "l"(a), "l"(b)); return d;
}
// HW tanh approximation (single MUFU op); accuracy validated at ~3e-7 rel.
__device__ __forceinline__ float tanh_hw(float x) {
    float y; asm("tanh.approx.f32 %0, %1;" : "=f"(y) : "f"(x)); return y;
}

// ---------------- kernel 1: build proxies ----------------
__global__ void proxy_kernel(
    const float* __restrict__ gb, const float* __restrict__ sup,
    const float* __restrict__ wi_w, const float* __restrict__ m_w,
    const float* __restrict__ n_w, const float* __restrict__ wo_w,
    const float* __restrict__ wi_b, const float* __restrict__ m_b,
    const float* __restrict__ n_b, const float* __restrict__ h0_w)
{
    int h = blockIdx.x * blockDim.x + threadIdx.x;
    if (h >= H_DIM) return;

    float gbh[GB_DIM];
#pragma unroll
    for (int g = 0; g < GB_DIM; ++g) gbh[g] = gb[g * H_DIM + h];
    float sv[S_DIM];
#pragma unroll
    for (int s = 0; s < S_DIM; ++s) sv[s] = sup[s * H_DIM + h];

#pragma unroll
    for (int i = 0; i < I_DIM; ++i) {
        float acc = 0.f;
#pragma unroll
        for (int s = 0; s < S_DIM; ++s) {
            float d = 0.f;
#pragma unroll
            for (int g = 0; g < GB_DIM; ++g)
                d = fmaf(wi_w[(i * S_DIM + s) * GB_DIM + g], gbh[g], d);
            acc = fmaf(sv[s], d, acc);
            acc = fmaf(wi_b[i * S_DIM + s], sv[s], acc);
        }
        g_wi[i * H_DIM + h] = ALPHA_C * acc;
    }

#pragma unroll
    for (int r = 0; r < R_DIM; ++r) {
        float am = 0.f, an = 0.f;
#pragma unroll
        for (int s = 0; s < S_DIM; ++s) {
            float dm = 0.f, dn = 0.f;
#pragma unroll
            for (int g = 0; g < GB_DIM; ++g) {
                dm = fmaf(m_w[(r * S_DIM + s) * GB_DIM + g], gbh[g], dm);
                dn = fmaf(n_w[(r * S_DIM + s) * GB_DIM + g], gbh[g], dn);
            }
            am = fmaf(sv[s], dm, am);
            am = fmaf(m_b[r * S_DIM + s], sv[s], am);
            an = fmaf(sv[s], dn, an);
            an = fmaf(n_b[r * S_DIM + s], sv[s], an);
        }
        g_m[r * H_DIM + h] = (ALPHA_C / (float)H_DIM) * am;
        g_n[r * H_DIM + h] = an;
    }

#pragma unroll
    for (int o = 0; o < O_DIM; ++o) {
        float ao = 0.f;
#pragma unroll
        for (int s = 0; s < S_DIM; ++s) {
            float d = 0.f;
#pragma unroll
            for (int g = 0; g < GB_DIM; ++g)
                d = fmaf(wo_w[(o * S_DIM + s) * GB_DIM + g], gbh[g], d);
            ao = fmaf(sv[s], d, ao);
        }
        g_wo[o * H_DIM + h] = ao * (1.0f / (float)H_DIM);
    }

    {
        float ah = 0.f;
#pragma unroll
        for (int s = 0; s < S_DIM; ++s) {
            float d = 0.f;
#pragma unroll
            for (int g = 0; g < GB_DIM; ++g)
                d = fmaf(h0_w[s * GB_DIM + g], gbh[g], d);
            ah = fmaf(sv[s], d, ah);
        }
        g_h0[h] = ah;
    }
}

// ---------------- kernel 2: sequential RNN scan, one CTA per batch ----------------
__global__ void __launch_bounds__(NTHREADS, 1)
rnn_kernel(const float* __restrict__ input,   // (B, T, I)
           const float* __restrict__ noise,   // (B, T, H)
           float* __restrict__ traj)          // (B, T, H)
{
    const int b    = blockIdx.x;
    const int tid  = threadIdx.x;
    const int lane = tid & 31;
    const int wid  = tid >> 5;
    const int j0   = tid * EPT;

    // double-buffered per-warp packed partials (p0,p1): 16 u64 per buffer
    __shared__ __align__(16) u64 pbuf[2][NWARPS];

    // --- load per-element weights, packed ---
    u64 wi_p[I_DIM][2];          // alpha*wi, pairs (e0,e1),(e2,e3)
#pragma unroll
    for (int i = 0; i < I_DIM; ++i) {
        float4 v = *reinterpret_cast<const float4*>(&g_wi[i * H_DIM + j0]);
        wi_p[i][0] = pack2(v.x, v.y);
        wi_p[i][1] = pack2(v.z, v.w);
    }
    u64 m0_p[2], m1_p[2];
    {
        float4 v;
        v = *reinterpret_cast<const float4*>(&g_m[0 * H_DIM + j0]);
        m0_p[0] = pack2(v.x, v.y); m0_p[1] = pack2(v.z, v.w);
        v = *reinterpret_cast<const float4*>(&g_m[1 * H_DIM + j0]);
        m1_p[0] = pack2(v.x, v.y); m1_p[1] = pack2(v.z, v.w);
    }
    u64 n01_p[EPT];              // per element e: (n0[e], n1[e]) packed
    {
        float4 a = *reinterpret_cast<const float4*>(&g_n[0 * H_DIM + j0]);
        float4 c = *reinterpret_cast<const float4*>(&g_n[1 * H_DIM + j0]);
        n01_p[0] = pack2(a.x, c.x);
        n01_p[1] = pack2(a.y, c.y);
        n01_p[2] = pack2(a.z, c.z);
        n01_p[3] = pack2(a.w, c.w);
    }

    const u64 SIG2 = dup2(SIGMA_C);
    const u64 C08  = dup2(1.0f - ALPHA_C);

    // --- state ---
    u64 h01, h23;
    float r0, r1, r2, r3;
    {
        float4 v = *reinterpret_cast<const float4*>(&g_h0[j0]);
        h01 = pack2(v.x, v.y);
        h23 = pack2(v.z, v.w);
        r0 = tanh_hw(v.x); r1 = tanh_hw(v.y);
        r2 = tanh_hw(v.z); r3 = tanh_hw(v.w);
    }

    const float* nrow = noise + ((size_t)b * T_DIM) * H_DIM + j0;
    const float* irow = input + (size_t)b * T_DIM * I_DIM;
    float*       trow = traj  + ((size_t)b * T_DIM) * H_DIM + j0;

    // prefetch step 0
    ulonglong2 nz = __ldg(reinterpret_cast<const ulonglong2*>(nrow));
    float4     iv = __ldg(reinterpret_cast<const float4*>(irow));

    const int parity4 = (lane & 1) * 4;   // even lanes sum warps 0-7, odd 8-15

    __syncthreads();

#pragma unroll 4
    for (int t = 0; t < T_DIM; ++t) {
        const int buf = t & 1;

        // prefetch next step, branchless (clamped; last-row re-read is dead data)
        const int tn = min(t + 1, T_DIM - 1);
        ulonglong2 nz_n = __ldg(reinterpret_cast<const ulonglong2*>(nrow + (size_t)tn * H_DIM));
        float4     iv_n = __ldg(reinterpret_cast<const float4*>(irow + (size_t)tn * I_DIM));

        // packed dot, two independent 2-deep chains:
        // (p0_partial, p1_partial) = sum_e r_e * (n0[e], n1[e])
        u64 accA = mul2(dup2(r0), n01_p[0]);
        u64 accB = mul2(dup2(r1), n01_p[1]);
        accA = fma2(dup2(r2), n01_p[2], accA);
        accB = fma2(dup2(r3), n01_p[3], accB);

        // butterfly round 1 split across the two chains (merge absorbed into round 1)
        u64 acc = add2(add2(accA, __shfl_xor_sync(0xffffffffu, accA, 16)),
                       add2(accB, __shfl_xor_sync(0xffffffffu, accB, 16)));
        // rounds 2..5
#pragma unroll
        for (int o = 8; o > 0; o >>= 1)
            acc = add2(acc, __shfl_xor_sync(0xffffffffu, acc, o));

        // every lane holds the full warp sum -> unconditional same-address STS
        pbuf[buf][wid] = acc;

        // u-part of the update (independent of P) — issued before the barrier
        const u64 ivx = dup2(iv.x), ivy = dup2(iv.y), ivz = dup2(iv.z), ivw = dup2(iv.w);
        u64 u0 = mul2(ivw, wi_p[3][0]);
        u64 u1 = mul2(ivw, wi_p[3][1]);
        u0 = fma2(ivz, wi_p[2][0], u0);
        u1 = fma2(ivz, wi_p[2][1], u1);
        u0 = fma2(ivy, wi_p[1][0], u0);
        u1 = fma2(ivy, wi_p[1][1], u1);
        u0 = fma2(ivx, wi_p[0][0], u0);
        u1 = fma2(ivx, wi_p[0][1], u1);
        u0 = fma2(nz.x, SIG2, u0);
        u1 = fma2(nz.y, SIG2, u1);

        __syncthreads();

        // final sum of 16 warp partials, parity-split:
        // even lanes sum warps 0-7, odd lanes warps 8-15; merge via 1 u64 shfl.
        u64 P;
        {
            const ulonglong2* pb = reinterpret_cast<const ulonglong2*>(&pbuf[buf][0]);
            ulonglong2 a = pb[parity4 + 0], c = pb[parity4 + 1];
            ulonglong2 d = pb[parity4 + 2], e = pb[parity4 + 3];
            u64 s0 = add2(a.x, a.y);
            u64 s1 = add2(c.x, c.y);
            u64 s2 = add2(d.x, d.y);
            u64 s3 = add2(e.x, e.y);
            u64 half = add2(add2(s0, s1), add2(s2, s3));
            u64 other = __shfl_xor_sync(0xffffffffu, half, 1);
            P = add2(half, other);          // (p0, p1) over all 16 warps
        }
        float p0, p1; unpack2(P, p0, p1);
        const u64 P0 = dup2(p0), P1 = dup2(p1);

        // finish h update
        u0 = fma2(P0, m0_p[0], u0);
        u1 = fma2(P0, m0_p[1], u1);
        u0 = fma2(P1, m1_p[0], u0);
        u1 = fma2(P1, m1_p[1], u1);
        h01 = fma2(h01, C08, u0);
        h23 = fma2(h23, C08, u1);

        // store trajectory (h) immediately — fire-and-forget into the MUFU shadow
        {
            ulonglong2 st; st.x = h01; st.y = h23;
            *reinterpret_cast<ulonglong2*>(trow + (size_t)t * H_DIM) = st;
        }

        // tanh for next step (HW approx, single MUFU each)
        {
            float a0, a1, a2, a3;
            unpack2(h01, a0, a1);
            unpack2(h23, a2, a3);
            r0 = tanh_hw(a0); r1 = tanh_hw(a1);
            r2 = tanh_hw(a2); r3 = tanh_hw(a3);
        }

        nz = nz_n;
        iv = iv_n;
    }
}

// ---------------- kernel 3: outputs from trajectories (full chip, bw-bound) ----------------
#define OUT_THREADS 256
__global__ void __launch_bounds__(OUT_THREADS)
out_kernel(const float* __restrict__ traj,  // (B*T, H)
           float* __restrict__ out)         // (B*T, O)
{
    const int bt  = blockIdx.x;
    const int tid = threadIdx.x;
    const int lane = tid & 31;
    const int wid  = tid >> 5;

    const float4* row = reinterpret_cast<const float4*>(traj + (size_t)bt * H_DIM);
    const float4* w0  = reinterpret_cast<const float4*>(g_wo);
    const float4* w1  = reinterpret_cast<const float4*>(g_wo + H_DIM);

    float q0 = 0.f, q1 = 0.f;
#pragma unroll
    for (int k = 0; k < 2; ++k) {
        int idx = k * OUT_THREADS + tid;             // 0..511 float4s
        float4 v = __ldg(&row[idx]);
        float4 a = w0[idx];
        float4 c = w1[idx];
        float t0 = tanh_hw(v.x), t1 = tanh_hw(v.y);
        float t2 = tanh_hw(v.z), t3 = tanh_hw(v.w);
        q0 = fmaf(t0, a.x, fmaf(t1, a.y, fmaf(t2, a.z, fmaf(t3, a.w, q0))));
        q1 = fmaf(t0, c.x, fmaf(t1, c.y, fmaf(t2, c.z, fmaf(t3, c.w, q1))));
    }
#pragma unroll
    for (int o = 16; o > 0; o >>= 1) {
        q0 += __shfl_xor_sync(0xffffffffu, q0, o);
        q1 += __shfl_xor_sync(0xffffffffu, q1, o);
    }
    __shared__ float2 s[8];
    if (lane == 0) s[wid] = make_float2(q0, q1);
    __syncthreads();
    if (wid == 0) {
        float2 v = (lane < 8) ? s[lane] : make_float2(0.f, 0.f);
#pragma unroll
        for (int o = 4; o > 0; o >>= 1) {
            v.x += __shfl_xor_sync(0xffffffffu, v.x, o);
            v.y += __shfl_xor_sync(0xffffffffu, v.y, o);
        }
        if (lane == 0) {
            out[(size_t)bt * O_DIM + 0] = v.x;
            out[(size_t)bt * O_DIM + 1] = v.y;
        }
    }
}

// ---------------- launcher ----------------
extern "C" void kernel_launch(void* const* d_in, const int* in_sizes, int n_in,
                              void* d_out, int out_size) {
    const float* input = (const float*)d_in[0];   // (B,T,I)
    const float* noise = (const float*)d_in[1];   // (B,T,H)
    const float* gb    = (const float*)d_in[2];   // (GB,H)
    const float* sup   = (const float*)d_in[3];   // (S,H)
    const float* wi_w  = (const float*)d_in[4];   // (I,S,GB)
    const float* m_w   = (const float*)d_in[5];   // (R,S,GB)
    const float* n_w   = (const float*)d_in[6];   // (R,S,GB)
    const float* wo_w  = (const float*)d_in[7];   // (O,S,GB)
    const float* wi_b  = (const float*)d_in[8];   // (I,S)
    const float* m_b   = (const float*)d_in[9];   // (R,S)
    const float* n_b   = (const float*)d_in[10];  // (R,S)
    const float* h0_w  = (const float*)d_in[11];  // (S,GB)

    float* out  = (float*)d_out;                                   // (B,T,O)
    float* traj = (float*)d_out + (size_t)B_DIM * T_DIM * O_DIM;   // (B,T,H)

    proxy_kernel<<<(H_DIM + 255) / 256, 256>>>(gb, sup, wi_w, m_w, n_w, wo_w,
                                               wi_b, m_b, n_b, h0_w);
    rnn_kernel<<<B_DIM, NTHREADS>>>(input, noise, traj);
    out_kernel<<<B_DIM * T_DIM, OUT_THREADS>>>(traj, out);
}

// round 17
// speedup vs baseline: 1.0903x; 1.0903x over previous
#include <cuda_runtime.h>
#include <cstdint>
#include <cstddef>

// ---------------- problem dims (fixed) ----------------
#define I_DIM   4
#define H_DIM   2048
#define O_DIM   2
#define R_DIM   2
#define S_DIM   2
#define GB_DIM  8
#define B_DIM   32
#define T_DIM   1024
#define ALPHA_C 0.2f
#define SIGMA_C 0.05f

#define NTHREADS 512
#define EPT      4          // neurons per thread: 512*4 = 2048
#define NWARPS   (NTHREADS / 32)   // 16

typedef unsigned long long u64;

// ---------------- precomputed proxy weights (device scratch) ----------------
__device__ __align__(16) float g_wi[I_DIM * H_DIM];  // alpha * wi,   layout [i][h]
__device__ __align__(16) float g_m [R_DIM * H_DIM];  // (alpha/H)*m,  layout [r][h]
__device__ __align__(16) float g_n [R_DIM * H_DIM];  // n (raw),      layout [r][h]
__device__ __align__(16) float g_wo[O_DIM * H_DIM];  // wo / H,       layout [o][h]
__device__ __align__(16) float g_h0[H_DIM];

// ---------------- packed f32x2 helpers (sm_103a) ----------------
__device__ __forceinline__ u64 pack2(float lo, float hi) {
    u64 r; asm("mov.b64 %0, {%1, %2};" : "=l"(r) : "f"(lo), "f"(hi)); return r;
}
__device__ __forceinline__ u64 dup2(float x) { return pack2(x, x); }
__device__ __forceinline__ void unpack2(u64 v, float& lo, float& hi) {
    asm("mov.b64 {%0, %1}, %2;" : "=f"(lo), "=f"(hi) : "l"(v));
}
__device__ __forceinline__ u64 fma2(u64 a, u64 b, u64 c) {
    u64 d; asm("fma.rn.f32x2 %0, %1, %2, %3;" : "=l"(d) : "l"(a), "l"(b), "l"(c)); return d;
}
__device__ __forceinline__ u64 mul2(u64 a, u64 b) {
    u64 d; asm("mul.rn.f32x2 %0, %1, %2;" : "=l"(d) : "l"(a), "l"(b)); return d;
}
__device__ __forceinline__ u64 add2(u64 a, u64 b) {
    u64 d; asm("add.rn.f32x2 %0, %1, %2;" : "=l"(d) : "l"(a), "l"(b)); return d;
}
// HW tanh approximation (single MUFU op); accuracy validated at ~3e-7 rel.
__device__ __forceinline__ float tanh_hw(float x) {
    float y; asm("tanh.approx.f32 %0, %1;" : "=f"(y) : "f"(x)); return y;
}

// ---------------- kernel 1: build proxies ----------------
__global__ void proxy_kernel(
    const float* __restrict__ gb, const float* __restrict__ sup,
    const float* __restrict__ wi_w, const float* __restrict__ m_w,
    const float* __restrict__ n_w, const float* __restrict__ wo_w,
    const float* __restrict__ wi_b, const float* __restrict__ m_b,
    const float* __restrict__ n_b, const float* __restrict__ h0_w)
{
    int h = blockIdx.x * blockDim.x + threadIdx.x;
    if (h >= H_DIM) return;

    float gbh[GB_DIM];
#pragma unroll
    for (int g = 0; g < GB_DIM; ++g) gbh[g] = gb[g * H_DIM + h];
    float sv[S_DIM];
#pragma unroll
    for (int s = 0; s < S_DIM; ++s) sv[s] = sup[s * H_DIM + h];

#pragma unroll
    for (int i = 0; i < I_DIM; ++i) {
        float acc = 0.f;
#pragma unroll
        for (int s = 0; s < S_DIM; ++s) {
            float d = 0.f;
#pragma unroll
            for (int g = 0; g < GB_DIM; ++g)
                d = fmaf(wi_w[(i * S_DIM + s) * GB_DIM + g], gbh[g], d);
            acc = fmaf(sv[s], d, acc);
            acc = fmaf(wi_b[i * S_DIM + s], sv[s], acc);
        }
        g_wi[i * H_DIM + h] = ALPHA_C * acc;
    }

#pragma unroll
    for (int r = 0; r < R_DIM; ++r) {
        float am = 0.f, an = 0.f;
#pragma unroll
        for (int s = 0; s < S_DIM; ++s) {
            float dm = 0.f, dn = 0.f;
#pragma unroll
            for (int g = 0; g < GB_DIM; ++g) {
                dm = fmaf(m_w[(r * S_DIM + s) * GB_DIM + g], gbh[g], dm);
                dn = fmaf(n_w[(r * S_DIM + s) * GB_DIM + g], gbh[g], dn);
            }
            am = fmaf(sv[s], dm, am);
            am = fmaf(m_b[r * S_DIM + s], sv[s], am);
            an = fmaf(sv[s], dn, an);
            an = fmaf(n_b[r * S_DIM + s], sv[s], an);
        }
        g_m[r * H_DIM + h] = (ALPHA_C / (float)H_DIM) * am;
        g_n[r * H_DIM + h] = an;
    }

#pragma unroll
    for (int o = 0; o < O_DIM; ++o) {
        float ao = 0.f;
#pragma unroll
        for (int s = 0; s < S_DIM; ++s) {
            float d = 0.f;
#pragma unroll
            for (int g = 0; g < GB_DIM; ++g)
                d = fmaf(wo_w[(o * S_DIM + s) * GB_DIM + g], gbh[g], d);
            ao = fmaf(sv[s], d, ao);
        }
        g_wo[o * H_DIM + h] = ao * (1.0f / (float)H_DIM);
    }

    {
        float ah = 0.f;
#pragma unroll
        for (int s = 0; s < S_DIM; ++s) {
            float d = 0.f;
#pragma unroll
            for (int g = 0; g < GB_DIM; ++g)
                d = fmaf(h0_w[s * GB_DIM + g], gbh[g], d);
            ah = fmaf(sv[s], d, ah);
        }
        g_h0[h] = ah;
    }
}

// ---------------- kernel 2: sequential RNN scan, one CTA per batch ----------------
__global__ void __launch_bounds__(NTHREADS, 1)
rnn_kernel(const float* __restrict__ input,   // (B, T, I)
           const float* __restrict__ noise,   // (B, T, H)
           float* __restrict__ traj)          // (B, T, H)
{
    const int b    = blockIdx.x;
    const int tid  = threadIdx.x;
    const int lane = tid & 31;
    const int wid  = tid >> 5;
    const int j0   = tid * EPT;

    // double-buffered per-warp packed partials (p0,p1): 16 u64 per buffer
    __shared__ __align__(16) u64 pbuf[2][NWARPS];

    // --- load per-element weights, packed ---
    u64 wi_p[I_DIM][2];          // alpha*wi, pairs (e0,e1),(e2,e3)
#pragma unroll
    for (int i = 0; i < I_DIM; ++i) {
        float4 v = *reinterpret_cast<const float4*>(&g_wi[i * H_DIM + j0]);
        wi_p[i][0] = pack2(v.x, v.y);
        wi_p[i][1] = pack2(v.z, v.w);
    }
    u64 m0_p[2], m1_p[2];
    {
        float4 v;
        v = *reinterpret_cast<const float4*>(&g_m[0 * H_DIM + j0]);
        m0_p[0] = pack2(v.x, v.y); m0_p[1] = pack2(v.z, v.w);
        v = *reinterpret_cast<const float4*>(&g_m[1 * H_DIM + j0]);
        m1_p[0] = pack2(v.x, v.y); m1_p[1] = pack2(v.z, v.w);
    }
    u64 n01_p[EPT];              // per element e: (n0[e], n1[e]) packed
    {
        float4 a = *reinterpret_cast<const float4*>(&g_n[0 * H_DIM + j0]);
        float4 c = *reinterpret_cast<const float4*>(&g_n[1 * H_DIM + j0]);
        n01_p[0] = pack2(a.x, c.x);
        n01_p[1] = pack2(a.y, c.y);
        n01_p[2] = pack2(a.z, c.z);
        n01_p[3] = pack2(a.w, c.w);
    }

    const u64 SIG2 = dup2(SIGMA_C);
    const u64 C08  = dup2(1.0f - ALPHA_C);

    // --- state ---
    u64 h01, h23;
    float r0, r1, r2, r3;
    {
        float4 v = *reinterpret_cast<const float4*>(&g_h0[j0]);
        h01 = pack2(v.x, v.y);
        h23 = pack2(v.z, v.w);
        r0 = tanh_hw(v.x); r1 = tanh_hw(v.y);
        r2 = tanh_hw(v.z); r3 = tanh_hw(v.w);
    }

    const float* nrow = noise + ((size_t)b * T_DIM) * H_DIM + j0;
    const float* irow = input + (size_t)b * T_DIM * I_DIM;
    float*       trow = traj  + ((size_t)b * T_DIM) * H_DIM + j0;

    // prefetch step 0
    ulonglong2 nz = __ldg(reinterpret_cast<const ulonglong2*>(nrow));
    float4     iv = __ldg(reinterpret_cast<const float4*>(irow));

    const int parity4 = (lane & 1) * 4;   // even lanes sum warps 0-7, odd 8-15

    __syncthreads();

#pragma unroll 2
    for (int t = 0; t < T_DIM; ++t) {
        const int buf = t & 1;

        // prefetch next step, branchless (clamped; last-row re-read is dead data)
        const int tn = min(t + 1, T_DIM - 1);
        ulonglong2 nz_n = __ldg(reinterpret_cast<const ulonglong2*>(nrow + (size_t)tn * H_DIM));
        float4     iv_n = __ldg(reinterpret_cast<const float4*>(irow + (size_t)tn * I_DIM));

        // packed dot, two independent 2-deep chains:
        // acc = (p0_partial, p1_partial) = sum_e r_e * (n0[e], n1[e])
        u64 accA = mul2(dup2(r0), n01_p[0]);
        u64 accB = mul2(dup2(r1), n01_p[1]);
        accA = fma2(dup2(r2), n01_p[2], accA);
        accB = fma2(dup2(r3), n01_p[3], accB);
        u64 acc = add2(accA, accB);

        // warp butterfly on packed value (5 rounds, pure adds, branch-free)
#pragma unroll
        for (int o = 16; o > 0; o >>= 1)
            acc = add2(acc, __shfl_xor_sync(0xffffffffu, acc, o));

        if (lane == 0) pbuf[buf][wid] = acc;

        // u-part of the update (independent of P) — issued before the barrier
        const u64 ivx = dup2(iv.x), ivy = dup2(iv.y), ivz = dup2(iv.z), ivw = dup2(iv.w);
        u64 u0 = mul2(ivw, wi_p[3][0]);
        u64 u1 = mul2(ivw, wi_p[3][1]);
        u0 = fma2(ivz, wi_p[2][0], u0);
        u1 = fma2(ivz, wi_p[2][1], u1);
        u0 = fma2(ivy, wi_p[1][0], u0);
        u1 = fma2(ivy, wi_p[1][1], u1);
        u0 = fma2(ivx, wi_p[0][0], u0);
        u1 = fma2(ivx, wi_p[0][1], u1);
        u0 = fma2(nz.x, SIG2, u0);
        u1 = fma2(nz.y, SIG2, u1);

        __syncthreads();

        // final sum of 16 warp partials, parity-split:
        // even lanes sum warps 0-7, odd lanes warps 8-15; merge via 1 u64 shfl.
        u64 P;
        {
            const ulonglong2* pb = reinterpret_cast<const ulonglong2*>(&pbuf[buf][0]);
            ulonglong2 a = pb[parity4 + 0], c = pb[parity4 + 1];
            ulonglong2 d = pb[parity4 + 2], e = pb[parity4 + 3];
            u64 s0 = add2(a.x, a.y);
            u64 s1 = add2(c.x, c.y);
            u64 s2 = add2(d.x, d.y);
            u64 s3 = add2(e.x, e.y);
            u64 half = add2(add2(s0, s1), add2(s2, s3));
            u64 other = __shfl_xor_sync(0xffffffffu, half, 1);
            P = add2(half, other);          // (p0, p1) over all 16 warps
        }
        float p0, p1; unpack2(P, p0, p1);
        const u64 P0 = dup2(p0), P1 = dup2(p1);

        // finish h update
        u0 = fma2(P0, m0_p[0], u0);
        u1 = fma2(P0, m0_p[1], u1);
        u0 = fma2(P1, m1_p[0], u0);
        u1 = fma2(P1, m1_p[1], u1);
        h01 = fma2(h01, C08, u0);
        h23 = fma2(h23, C08, u1);

        // store trajectory (h) immediately — fire-and-forget into the MUFU shadow
        {
            ulonglong2 st; st.x = h01; st.y = h23;
            *reinterpret_cast<ulonglong2*>(trow + (size_t)t * H_DIM) = st;
        }

        // tanh for next step (HW approx, single MUFU each)
        {
            float a0, a1, a2, a3;
            unpack2(h01, a0, a1);
            unpack2(h23, a2, a3);
            r0 = tanh_hw(a0); r1 = tanh_hw(a1);
            r2 = tanh_hw(a2); r3 = tanh_hw(a3);
        }

        nz = nz_n;
        iv = iv_n;
    }
}

// ---------------- kernel 3: outputs from trajectories (full chip, bw-bound) ----------------
#define OUT_THREADS 256
__global__ void __launch_bounds__(OUT_THREADS)
out_kernel(const float* __restrict__ traj,  // (B*T, H)
           float* __restrict__ out)         // (B*T, O)
{
    const int bt  = blockIdx.x;
    const int tid = threadIdx.x;
    const int lane = tid & 31;
    const int wid  = tid >> 5;

    const float4* row = reinterpret_cast<const float4*>(traj + (size_t)bt * H_DIM);
    const float4* w0  = reinterpret_cast<const float4*>(g_wo);
    const float4* w1  = reinterpret_cast<const float4*>(g_wo + H_DIM);

    float q0 = 0.f, q1 = 0.f;
#pragma unroll
    for (int k = 0; k < 2; ++k) {
        int idx = k * OUT_THREADS + tid;             // 0..511 float4s
        float4 v = __ldg(&row[idx]);
        float4 a = w0[idx];
        float4 c = w1[idx];
        float t0 = tanh_hw(v.x), t1 = tanh_hw(v.y);
        float t2 = tanh_hw(v.z), t3 = tanh_hw(v.w);
        q0 = fmaf(t0, a.x, fmaf(t1, a.y, fmaf(t2, a.z, fmaf(t3, a.w, q0))));
        q1 = fmaf(t0, c.x, fmaf(t1, c.y, fmaf(t2, c.z, fmaf(t3, c.w, q1))));
    }
#pragma unroll
    for (int o = 16; o > 0; o >>= 1) {
        q0 += __shfl_xor_sync(0xffffffffu, q0, o);
        q1 += __shfl_xor_sync(0xffffffffu, q1, o);
    }
    __shared__ float2 s[8];
    if (lane == 0) s[wid] = make_float2(q0, q1);
    __syncthreads();
    if (wid == 0) {
        float2 v = (lane < 8) ? s[lane] : make_float2(0.f, 0.f);
#pragma unroll
        for (int o = 4; o > 0; o >>= 1) {
            v.x += __shfl_xor_sync(0xffffffffu, v.x, o);
            v.y += __shfl_xor_sync(0xffffffffu, v.y, o);
        }
        if (lane == 0) {
            out[(size_t)bt * O_DIM + 0] = v.x;
            out[(size_t)bt * O_DIM + 1] = v.y;
        }
    }
}

// ---------------- launcher ----------------
extern "C" void kernel_launch(void* const* d_in, const int* in_sizes, int n_in,
                              void* d_out, int out_size) {
    const float* input = (const float*)d_in[0];   // (B,T,I)
    const float* noise = (const float*)d_in[1];   // (B,T,H)
    const float* gb    = (const float*)d_in[2];   // (GB,H)
    const float* sup   = (const float*)d_in[3];   // (S,H)
    const float* wi_w  = (const float*)d_in[4];   // (I,S,GB)
    const float* m_w   = (const float*)d_in[5];   // (R,S,GB)
    const float* n_w   = (const float*)d_in[6];   // (R,S,GB)
    const float* wo_w  = (const float*)d_in[7];   // (O,S,GB)
    const float* wi_b  = (const float*)d_in[8];   // (I,S)
    const float* m_b   = (const float*)d_in[9];   // (R,S)
    const float* n_b   = (const float*)d_in[10];  // (R,S)
    const float* h0_w  = (const float*)d_in[11];  // (S,GB)

    float* out  = (float*)d_out;                                   // (B,T,O)
    float* traj = (float*)d_out + (size_t)B_DIM * T_DIM * O_DIM;   // (B,T,H)

    proxy_kernel<<<(H_DIM + 255) / 256, 256>>>(gb, sup, wi_w, m_w, n_w, wo_w,
                                               wi_b, m_b, n_b, h0_w);
    rnn_kernel<<<B_DIM, NTHREADS>>>(input, noise, traj);
    out_kernel<<<B_DIM * T_DIM, OUT_THREADS>>>(traj, out);
}